// round 9
// baseline (speedup 1.0000x reference)
#include <cuda_runtime.h>
#include <cuda_fp16.h>
#include <cstdint>
#include <cstddef>

#define BATCH 16384
#define HDIM  512
#define ODIM  128
#define NEXP  5
#define NZ    15

#define BM    128
#define BN    128
#define BK    64             // halfs per k-tile (128B rows)
#define NKT   (HDIM/BK)      // 8
#define STAGES 3
#define NTH   256
#define A_OFF 0
#define B_OFF 16384
#define STAGE_BYTES 32768    // 16KB A + 16KB B

// device scratch (static; allocation-guard-safe)
__device__ __half g_Xh [(size_t)3  * BATCH * HDIM];   // fp16 inputs  [bank][m][k]
__device__ __half g_H  [(size_t)NZ * BATCH * HDIM];   // fp16 hidden  [z][m][k]
__device__ __half g_W1h[(size_t)NZ * HDIM * HDIM];    // fp16 [z][n][k] (transposed)
__device__ __half g_W2h[(size_t)NZ * ODIM * HDIM];    // fp16 [z][n][k] (transposed)

// ---------------------------------------------------------------------------
// helpers
// ---------------------------------------------------------------------------
__device__ __forceinline__ uint32_t smem_u32(const void* p) {
    uint32_t a;
    asm("{ .reg .u64 t; cvta.to.shared.u64 t, %1; cvt.u32.u64 %0, t; }" : "=r"(a) : "l"(p));
    return a;
}
__device__ __forceinline__ void cp16(uint32_t s, const void* g) {
    asm volatile("cp.async.cg.shared.global [%0], [%1], 16;\n" :: "r"(s), "l"(g));
}
__device__ __forceinline__ void cp_commit() { asm volatile("cp.async.commit_group;\n"); }
template<int N> __device__ __forceinline__ void cp_wait() {
    asm volatile("cp.async.wait_group %0;\n" :: "n"(N));
}
__device__ __forceinline__ void ldsm4(uint32_t& d0, uint32_t& d1, uint32_t& d2, uint32_t& d3,
                                      uint32_t a) {
    asm volatile("ldmatrix.sync.aligned.m8n8.x4.shared.b16 {%0,%1,%2,%3}, [%4];"
                 : "=r"(d0), "=r"(d1), "=r"(d2), "=r"(d3) : "r"(a));
}
__device__ __forceinline__ void mma16816(float& d0, float& d1, float& d2, float& d3,
                                         uint32_t a0, uint32_t a1, uint32_t a2, uint32_t a3,
                                         uint32_t b0, uint32_t b1) {
    asm volatile(
        "mma.sync.aligned.m16n8k16.row.col.f32.f16.f16.f32 "
        "{%0,%1,%2,%3}, {%4,%5,%6,%7}, {%8,%9}, {%0,%1,%2,%3};"
        : "+f"(d0), "+f"(d1), "+f"(d2), "+f"(d3)
        : "r"(a0), "r"(a1), "r"(a2), "r"(a3), "r"(b0), "r"(b1));
}

// ---------------------------------------------------------------------------
// conversion kernels (unchanged; validated numerics, rel_err 4.1e-4)
// ---------------------------------------------------------------------------
__global__ void cvt_x_kernel(const float* __restrict__ x0, const float* __restrict__ x1,
                             const float* __restrict__ x2)
{
    const size_t per = (size_t)BATCH * HDIM / 4;
    const size_t i = (size_t)blockIdx.x * blockDim.x + threadIdx.x;
    if (i >= 3 * per) return;
    const int bank = (int)(i / per);
    const size_t r = i - (size_t)bank * per;
    const float4 v = ((const float4*)(bank == 0 ? x0 : bank == 1 ? x1 : x2))[r];
    __half2 h0 = __floats2half2_rn(v.x, v.y);
    __half2 h1 = __floats2half2_rn(v.z, v.w);
    ((uint2*)g_Xh)[i] = make_uint2(*(uint32_t*)&h0, *(uint32_t*)&h1);
}

__global__ void cvt_w_kernel(const float* __restrict__ sW1, const float* __restrict__ tW1,
                             const float* __restrict__ sW2, const float* __restrict__ tW2)
{
    __shared__ float t[32][33];
    int b = blockIdx.x;
    const float* src; __half* dst; int N, n0, k0;
    if (b < NZ * 256) {                      // W1
        const int z = b >> 8, r = b & 255;
        n0 = (r >> 4) * 32; k0 = (r & 15) * 32;
        src = (z < NEXP) ? sW1 + (size_t)z * HDIM * HDIM
                         : tW1 + (size_t)(z - NEXP) * HDIM * HDIM;
        dst = g_W1h + (size_t)z * HDIM * HDIM;
        N = HDIM;
    } else {                                 // W2
        b -= NZ * 256;
        const int z = b >> 6, r = b & 63;
        k0 = (r >> 2) * 32; n0 = (r & 3) * 32;
        src = (z < NEXP) ? sW2 + (size_t)z * HDIM * ODIM
                         : tW2 + (size_t)(z - NEXP) * HDIM * ODIM;
        dst = g_W2h + (size_t)z * ODIM * HDIM;
        N = ODIM;
    }
    const int tx = threadIdx.x, ty = threadIdx.y;   // (32, 8)
    #pragma unroll
    for (int i = 0; i < 4; ++i)
        t[ty + i * 8][tx] = src[(size_t)(k0 + ty + i * 8) * N + n0 + tx];
    __syncthreads();
    #pragma unroll
    for (int i = 0; i < 4; ++i)
        dst[(size_t)(n0 + ty + i * 8) * HDIM + k0 + tx] = __float2half_rn(t[tx][ty + i * 8]);
}

// ---------------------------------------------------------------------------
// fp16 tensor-core GEMM body with m-tile chaining:
// one CTA computes MT consecutive C[128,128] tiles (along m) in ONE continuous
// cp.async pipeline — prologue paid once, epilogue of tile t overlaps the
// in-flight loads of tile t+1.
//   A : [*, 512] half row-major, W : [n_total, 512] half row-major
// ---------------------------------------------------------------------------
template<int MT, bool RELU, bool OUT_HALF, int LDC>
__device__ __forceinline__ void gemm_body(const __half* __restrict__ A,
                                          const __half* __restrict__ W,
                                          const float*  __restrict__ bias,
                                          void* __restrict__ Cout)
{
    __shared__ __align__(1024) char smem[STAGES * STAGE_BYTES];
    const uint32_t sb = smem_u32(smem);

    const int tid = threadIdx.x, lane = tid & 31, wid = tid >> 5;
    const int wm = wid >> 2, wn = wid & 3;
    const int bm0 = blockIdx.y * (BM * MT), bn = blockIdx.x * BN;

    // ---- cp.async mapping: 4 A + 4 B granules (16B) per thread per stage ----
    int arow[4], acol[4];                 // A: row-in-tile, k-granule
    const __half* Bg[4];
    uint32_t sAo[4], sBo[4];
    #pragma unroll
    for (int i = 0; i < 4; ++i) {
        const int idx = i * NTH + tid;
        const int r = idx >> 3, c = idx & 7;
        arow[i] = r; acol[i] = c;
        Bg[i] = W + (size_t)(bn + r) * HDIM + c * 8;
        const uint32_t o = (uint32_t)(r * 128 + ((c ^ (r & 7)) << 4));
        sAo[i] = A_OFF + o;
        sBo[i] = B_OFF + o;
    }

    // ---- fragment address tables (8-granule-row swizzle) ----
    const int ah = lane >> 4;
    uint32_t art[4]; int arx[4];
    #pragma unroll
    for (int mi = 0; mi < 4; ++mi) {
        const int r = wm * 64 + mi * 16 + (lane & 15);
        art[mi] = A_OFF + (uint32_t)(r * 128); arx[mi] = r & 7;
    }
    const int bh = (lane >> 3) & 1;
    uint32_t nrt[2]; int nrx[2];
    #pragma unroll
    for (int p = 0; p < 2; ++p) {
        const int r = wn * 32 + p * 16 + ((lane >> 4) << 3) + (lane & 7);
        nrt[p] = B_OFF + (uint32_t)(r * 128); nrx[p] = r & 7;
    }

    float acc[4][4][4] = {};

    // ---- prologue: fill 2 stages (tile 0, k-chunks 0,1) ----
    #pragma unroll
    for (int s = 0; s < STAGES - 1; ++s) {
        const uint32_t base = sb + s * STAGE_BYTES;
        #pragma unroll
        for (int i = 0; i < 4; ++i)
            cp16(base + sAo[i], A + (size_t)(bm0 + arow[i]) * HDIM + acol[i] * 8 + s * BK);
        #pragma unroll
        for (int i = 0; i < 4; ++i)
            cp16(base + sBo[i], Bg[i] + s * BK);
        cp_commit();
    }

    const int NJ = MT * NKT;
    #pragma unroll 1
    for (int j = 0; j < NJ; ++j) {
        cp_wait<STAGES - 2>();
        __syncthreads();

        const int jn = j + STAGES - 1;
        if (jn < NJ) {
            const int itn = jn >> 3, ktn = jn & 7;    // NKT == 8
            const uint32_t base = sb + (jn % STAGES) * STAGE_BYTES;
            const __half* An = A + (size_t)(bm0 + itn * BM) * HDIM + ktn * BK;
            #pragma unroll
            for (int i = 0; i < 4; ++i)
                cp16(base + sAo[i], An + (size_t)arow[i] * HDIM + acol[i] * 8);
            #pragma unroll
            for (int i = 0; i < 4; ++i)
                cp16(base + sBo[i], Bg[i] + ktn * BK);
        }
        cp_commit();

        const uint32_t stg = sb + (j % STAGES) * STAGE_BYTES;
        #pragma unroll
        for (int k16 = 0; k16 < 4; ++k16) {
            const int ga = k16 * 2 + ah;
            const int gb = k16 * 2 + bh;
            uint32_t af[4][4], bf[4][2];
            #pragma unroll
            for (int mi = 0; mi < 4; ++mi)
                ldsm4(af[mi][0], af[mi][1], af[mi][2], af[mi][3],
                      stg + art[mi] + ((uint32_t)(ga ^ arx[mi]) << 4));
            #pragma unroll
            for (int p = 0; p < 2; ++p)
                ldsm4(bf[2 * p][0], bf[2 * p][1], bf[2 * p + 1][0], bf[2 * p + 1][1],
                      stg + nrt[p] + ((uint32_t)(gb ^ nrx[p]) << 4));
            #pragma unroll
            for (int mi = 0; mi < 4; ++mi)
                #pragma unroll
                for (int ni = 0; ni < 4; ++ni)
                    mma16816(acc[mi][ni][0], acc[mi][ni][1], acc[mi][ni][2], acc[mi][ni][3],
                             af[mi][0], af[mi][1], af[mi][2], af[mi][3],
                             bf[ni][0], bf[ni][1]);
        }

        // ---- tile complete: epilogue overlaps next tile's in-flight loads ----
        if ((j & 7) == 7) {
            const int it = j >> 3;
            const int g = lane >> 2, t = lane & 3;
            #pragma unroll
            for (int mi = 0; mi < 4; ++mi) {
                const int r0g = bm0 + it * BM + wm * 64 + mi * 16 + g;
                const int r1g = r0g + 8;
                #pragma unroll
                for (int ni = 0; ni < 4; ++ni) {
                    const int c0g = bn + wn * 32 + ni * 8 + t * 2;
                    const float bv0 = bias[c0g], bv1 = bias[c0g + 1];
                    float v00 = acc[mi][ni][0] + bv0;
                    float v01 = acc[mi][ni][1] + bv1;
                    float v10 = acc[mi][ni][2] + bv0;
                    float v11 = acc[mi][ni][3] + bv1;
                    if (RELU) {
                        v00 = fmaxf(v00, 0.0f); v01 = fmaxf(v01, 0.0f);
                        v10 = fmaxf(v10, 0.0f); v11 = fmaxf(v11, 0.0f);
                    }
                    if (OUT_HALF) {
                        *(__half2*)&((__half*)Cout)[(size_t)r0g * LDC + c0g] = __floats2half2_rn(v00, v01);
                        *(__half2*)&((__half*)Cout)[(size_t)r1g * LDC + c0g] = __floats2half2_rn(v10, v11);
                    } else {
                        *(float2*)&((float*)Cout)[(size_t)r0g * LDC + c0g] = make_float2(v00, v01);
                        *(float2*)&((float*)Cout)[(size_t)r1g * LDC + c0g] = make_float2(v10, v11);
                    }
                    acc[mi][ni][0] = acc[mi][ni][1] = acc[mi][ni][2] = acc[mi][ni][3] = 0.0f;
                }
            }
        }
    }
}

// ---------------------------------------------------------------------------
// kernels
// ---------------------------------------------------------------------------
#define MT1 4   // gemm1: 4 m-tiles per CTA
#define MT2 2   // gemm2: 2 m-tiles per CTA

__global__ __launch_bounds__(NTH, 2)
void gemm1_kernel(const float* __restrict__ sb1, const float* __restrict__ tb1)
{
    const int z = blockIdx.z, bank = z / NEXP, e = z - bank * NEXP;
    const __half* A = g_Xh + (size_t)bank * BATCH * HDIM;
    const __half* W = g_W1h + (size_t)z * HDIM * HDIM;
    const float* bias = (bank == 0) ? sb1 + (size_t)e * HDIM
                                    : tb1 + ((size_t)(bank - 1) * NEXP + e) * HDIM;
    __half* C = g_H + (size_t)z * BATCH * HDIM;
    gemm_body<MT1, true, true, HDIM>(A, W, bias, C);
}

__global__ __launch_bounds__(NTH, 2)
void gemm2_kernel(const float* __restrict__ sb2, const float* __restrict__ tb2,
                  float* __restrict__ out)
{
    const int z = blockIdx.z, bank = z / NEXP, e = z - bank * NEXP;
    const __half* A = g_H + (size_t)z * BATCH * HDIM;
    const __half* W = g_W2h + (size_t)z * ODIM * HDIM;
    const float* bias = (bank == 0) ? sb2 + (size_t)e * ODIM
                                    : tb2 + ((size_t)(bank - 1) * NEXP + e) * ODIM;
    gemm_body<MT2, false, false, ODIM>(A, W, bias, out + (size_t)z * BATCH * ODIM);
}

// ---------------------------------------------------------------------------
// launch
// ---------------------------------------------------------------------------
extern "C" void kernel_launch(void* const* d_in, const int* in_sizes, int n_in,
                              void* d_out, int out_size)
{
    const float* share_x  = (const float*)d_in[0];
    const float* task_x0  = (const float*)d_in[1];
    const float* task_x1  = (const float*)d_in[2];
    const float* share_W1 = (const float*)d_in[3];
    const float* share_b1 = (const float*)d_in[4];
    const float* share_W2 = (const float*)d_in[5];
    const float* share_b2 = (const float*)d_in[6];
    const float* task_W1  = (const float*)d_in[7];
    const float* task_b1  = (const float*)d_in[8];
    const float* task_W2  = (const float*)d_in[9];
    const float* task_b2  = (const float*)d_in[10];
    float* out = (float*)d_out;

    // 1) convert inputs + transpose/convert weights to fp16
    const size_t nx4 = (size_t)3 * BATCH * HDIM / 4;
    cvt_x_kernel<<<(unsigned)((nx4 + 255) / 256), 256>>>(share_x, task_x0, task_x1);
    cvt_w_kernel<<<NZ * 256 + NZ * 64, dim3(32, 8)>>>(share_W1, task_W1, share_W2, task_W2);

    // 2) GEMMs (m-tile chained)
    gemm1_kernel<<<dim3(HDIM / BN, BATCH / (BM * MT1), NZ), NTH>>>(share_b1, task_b1);
    gemm2_kernel<<<dim3(ODIM / BN, BATCH / (BM * MT2), NZ), NTH>>>(share_b2, task_b2, out);
}

// round 10
// speedup vs baseline: 1.5470x; 1.5470x over previous
#include <cuda_runtime.h>
#include <cuda_fp16.h>
#include <cstdint>
#include <cstddef>

#define BATCH 16384
#define HDIM  512
#define ODIM  128
#define NEXP  5
#define NZ    15

#define BM    128
#define BN    128
#define BK    64             // halfs per k-tile (128B rows)
#define NKT   (HDIM/BK)      // 8
#define STAGES 3
#define NTH   128            // 4 warps, warp tile 64x64
#define A_OFF 0
#define B_OFF 16384
#define STAGE_BYTES 32768    // 16KB A + 16KB B

// device scratch (static; allocation-guard-safe)
__device__ __half g_Xh [(size_t)3  * BATCH * HDIM];   // fp16 inputs  [bank][m][k]
__device__ __half g_H  [(size_t)NZ * BATCH * HDIM];   // fp16 hidden  [z][m][k]
__device__ __half g_W1h[(size_t)NZ * HDIM * HDIM];    // fp16 [z][n][k] (transposed)
__device__ __half g_W2h[(size_t)NZ * ODIM * HDIM];    // fp16 [z][n][k] (transposed)

// ---------------------------------------------------------------------------
// helpers
// ---------------------------------------------------------------------------
__device__ __forceinline__ uint32_t smem_u32(const void* p) {
    uint32_t a;
    asm("{ .reg .u64 t; cvta.to.shared.u64 t, %1; cvt.u32.u64 %0, t; }" : "=r"(a) : "l"(p));
    return a;
}
__device__ __forceinline__ void cp16(uint32_t s, const void* g) {
    asm volatile("cp.async.cg.shared.global [%0], [%1], 16;\n" :: "r"(s), "l"(g));
}
__device__ __forceinline__ void cp_commit() { asm volatile("cp.async.commit_group;\n"); }
template<int N> __device__ __forceinline__ void cp_wait() {
    asm volatile("cp.async.wait_group %0;\n" :: "n"(N));
}
__device__ __forceinline__ void ldsm4(uint32_t& d0, uint32_t& d1, uint32_t& d2, uint32_t& d3,
                                      uint32_t a) {
    asm volatile("ldmatrix.sync.aligned.m8n8.x4.shared.b16 {%0,%1,%2,%3}, [%4];"
                 : "=r"(d0), "=r"(d1), "=r"(d2), "=r"(d3) : "r"(a));
}
__device__ __forceinline__ void mma16816(float& d0, float& d1, float& d2, float& d3,
                                         uint32_t a0, uint32_t a1, uint32_t a2, uint32_t a3,
                                         uint32_t b0, uint32_t b1) {
    asm volatile(
        "mma.sync.aligned.m16n8k16.row.col.f32.f16.f16.f32 "
        "{%0,%1,%2,%3}, {%4,%5,%6,%7}, {%8,%9}, {%0,%1,%2,%3};"
        : "+f"(d0), "+f"(d1), "+f"(d2), "+f"(d3)
        : "r"(a0), "r"(a1), "r"(a2), "r"(a3), "r"(b0), "r"(b1));
}

// ---------------------------------------------------------------------------
// conversion kernels (unchanged; validated numerics, rel_err 4.1e-4)
// ---------------------------------------------------------------------------
__global__ void cvt_x_kernel(const float* __restrict__ x0, const float* __restrict__ x1,
                             const float* __restrict__ x2)
{
    const size_t per = (size_t)BATCH * HDIM / 4;
    const size_t i = (size_t)blockIdx.x * blockDim.x + threadIdx.x;
    if (i >= 3 * per) return;
    const int bank = (int)(i / per);
    const size_t r = i - (size_t)bank * per;
    const float4 v = ((const float4*)(bank == 0 ? x0 : bank == 1 ? x1 : x2))[r];
    __half2 h0 = __floats2half2_rn(v.x, v.y);
    __half2 h1 = __floats2half2_rn(v.z, v.w);
    ((uint2*)g_Xh)[i] = make_uint2(*(uint32_t*)&h0, *(uint32_t*)&h1);
}

__global__ void cvt_w_kernel(const float* __restrict__ sW1, const float* __restrict__ tW1,
                             const float* __restrict__ sW2, const float* __restrict__ tW2)
{
    __shared__ float t[32][33];
    int b = blockIdx.x;
    const float* src; __half* dst; int N, n0, k0;
    if (b < NZ * 256) {                      // W1
        const int z = b >> 8, r = b & 255;
        n0 = (r >> 4) * 32; k0 = (r & 15) * 32;
        src = (z < NEXP) ? sW1 + (size_t)z * HDIM * HDIM
                         : tW1 + (size_t)(z - NEXP) * HDIM * HDIM;
        dst = g_W1h + (size_t)z * HDIM * HDIM;
        N = HDIM;
    } else {                                 // W2
        b -= NZ * 256;
        const int z = b >> 6, r = b & 63;
        k0 = (r >> 2) * 32; n0 = (r & 3) * 32;
        src = (z < NEXP) ? sW2 + (size_t)z * HDIM * ODIM
                         : tW2 + (size_t)(z - NEXP) * HDIM * ODIM;
        dst = g_W2h + (size_t)z * ODIM * HDIM;
        N = ODIM;
    }
    const int tx = threadIdx.x, ty = threadIdx.y;   // (32, 8)
    #pragma unroll
    for (int i = 0; i < 4; ++i)
        t[ty + i * 8][tx] = src[(size_t)(k0 + ty + i * 8) * N + n0 + tx];
    __syncthreads();
    #pragma unroll
    for (int i = 0; i < 4; ++i)
        dst[(size_t)(n0 + ty + i * 8) * HDIM + k0 + tx] = __float2half_rn(t[tx][ty + i * 8]);
}

// ---------------------------------------------------------------------------
// fp16 tensor-core GEMM body: C[128,128] tile, 4 warps, warp tile 64x64.
// Per k16 a warp issues 8 ldmatrix.x4 feeding 64 independent MMAs.
//   A : [*, 512] half row-major, W : [n_total, 512] half row-major
// ---------------------------------------------------------------------------
template<bool RELU, bool OUT_HALF, int LDC>
__device__ __forceinline__ void gemm_body(const __half* __restrict__ A,
                                          const __half* __restrict__ W,
                                          const float*  __restrict__ bias,
                                          void* __restrict__ Cout)
{
    __shared__ __align__(1024) char smem[STAGES * STAGE_BYTES];
    const uint32_t sb = smem_u32(smem);

    const int tid = threadIdx.x, lane = tid & 31, wid = tid >> 5;
    const int wm = wid >> 1, wn = wid & 1;               // warps 2m x 2n, tile 64x64
    const int bm = blockIdx.y * BM, bn = blockIdx.x * BN;

    // ---- cp.async mapping: 8 A + 8 B granules (16B) per thread per stage ----
    const __half* Ag[8]; const __half* Bg[8]; uint32_t sAo[8], sBo[8];
    #pragma unroll
    for (int i = 0; i < 8; ++i) {
        const int idx = i * NTH + tid;
        const int r = idx >> 3, c = idx & 7;
        Ag[i] = A + (size_t)(bm + r) * HDIM + c * 8;
        Bg[i] = W + (size_t)(bn + r) * HDIM + c * 8;
        const uint32_t o = (uint32_t)(r * 128 + ((c ^ (r & 7)) << 4));
        sAo[i] = A_OFF + o;
        sBo[i] = B_OFF + o;
    }

    // ---- fragment address tables (8-granule-row swizzle) ----
    const int ah = lane >> 4;            // A k-half select
    uint32_t art[4]; int arx[4];
    #pragma unroll
    for (int mi = 0; mi < 4; ++mi) {
        const int r = wm * 64 + mi * 16 + (lane & 15);
        art[mi] = A_OFF + (uint32_t)(r * 128); arx[mi] = r & 7;
    }
    const int bh = (lane >> 3) & 1;      // B k-half select
    uint32_t nrt[4]; int nrx[4];
    #pragma unroll
    for (int p = 0; p < 4; ++p) {
        const int r = wn * 64 + p * 16 + ((lane >> 4) << 3) + (lane & 7);
        nrt[p] = B_OFF + (uint32_t)(r * 128); nrx[p] = r & 7;
    }

    float acc[4][8][4] = {};

    // ---- prologue: fill 2 stages ----
    #pragma unroll
    for (int s = 0; s < STAGES - 1; ++s) {
        const int ko = s * BK;
        const uint32_t base = sb + s * STAGE_BYTES;
        #pragma unroll
        for (int i = 0; i < 8; ++i) { cp16(base + sAo[i], Ag[i] + ko); }
        #pragma unroll
        for (int i = 0; i < 8; ++i) { cp16(base + sBo[i], Bg[i] + ko); }
        cp_commit();
    }

    #pragma unroll 1
    for (int kt = 0; kt < NKT; ++kt) {
        cp_wait<STAGES - 2>();
        __syncthreads();

        if (kt + STAGES - 1 < NKT) {
            const int ko = (kt + STAGES - 1) * BK;
            const uint32_t base = sb + ((kt + STAGES - 1) % STAGES) * STAGE_BYTES;
            #pragma unroll
            for (int i = 0; i < 8; ++i) { cp16(base + sAo[i], Ag[i] + ko); }
            #pragma unroll
            for (int i = 0; i < 8; ++i) { cp16(base + sBo[i], Bg[i] + ko); }
        }
        cp_commit();

        const uint32_t stg = sb + (kt % STAGES) * STAGE_BYTES;
        #pragma unroll
        for (int k16 = 0; k16 < 4; ++k16) {
            const int ga = k16 * 2 + ah;
            const int gb = k16 * 2 + bh;
            uint32_t af[4][4], bf[8][2];
            #pragma unroll
            for (int mi = 0; mi < 4; ++mi)
                ldsm4(af[mi][0], af[mi][1], af[mi][2], af[mi][3],
                      stg + art[mi] + ((uint32_t)(ga ^ arx[mi]) << 4));
            #pragma unroll
            for (int p = 0; p < 4; ++p)
                ldsm4(bf[2 * p][0], bf[2 * p][1], bf[2 * p + 1][0], bf[2 * p + 1][1],
                      stg + nrt[p] + ((uint32_t)(gb ^ nrx[p]) << 4));
            #pragma unroll
            for (int mi = 0; mi < 4; ++mi)
                #pragma unroll
                for (int ni = 0; ni < 8; ++ni)
                    mma16816(acc[mi][ni][0], acc[mi][ni][1], acc[mi][ni][2], acc[mi][ni][3],
                             af[mi][0], af[mi][1], af[mi][2], af[mi][3],
                             bf[ni][0], bf[ni][1]);
        }
    }

    // ---- epilogue: bias (+relu), write ----
    const int g = lane >> 2, t = lane & 3;
    #pragma unroll
    for (int mi = 0; mi < 4; ++mi) {
        const int r0g = bm + wm * 64 + mi * 16 + g;
        const int r1g = r0g + 8;
        #pragma unroll
        for (int ni = 0; ni < 8; ++ni) {
            const int c0g = bn + wn * 64 + ni * 8 + t * 2;
            const float bv0 = bias[c0g], bv1 = bias[c0g + 1];
            float v00 = acc[mi][ni][0] + bv0;
            float v01 = acc[mi][ni][1] + bv1;
            float v10 = acc[mi][ni][2] + bv0;
            float v11 = acc[mi][ni][3] + bv1;
            if (RELU) {
                v00 = fmaxf(v00, 0.0f); v01 = fmaxf(v01, 0.0f);
                v10 = fmaxf(v10, 0.0f); v11 = fmaxf(v11, 0.0f);
            }
            if (OUT_HALF) {
                *(__half2*)&((__half*)Cout)[(size_t)r0g * LDC + c0g] = __floats2half2_rn(v00, v01);
                *(__half2*)&((__half*)Cout)[(size_t)r1g * LDC + c0g] = __floats2half2_rn(v10, v11);
            } else {
                *(float2*)&((float*)Cout)[(size_t)r0g * LDC + c0g] = make_float2(v00, v01);
                *(float2*)&((float*)Cout)[(size_t)r1g * LDC + c0g] = make_float2(v10, v11);
            }
        }
    }
}

// ---------------------------------------------------------------------------
// kernels
// ---------------------------------------------------------------------------
__global__ __launch_bounds__(NTH, 2)
void gemm1_kernel(const float* __restrict__ sb1, const float* __restrict__ tb1)
{
    const int z = blockIdx.z, bank = z / NEXP, e = z - bank * NEXP;
    const __half* A = g_Xh + (size_t)bank * BATCH * HDIM;
    const __half* W = g_W1h + (size_t)z * HDIM * HDIM;
    const float* bias = (bank == 0) ? sb1 + (size_t)e * HDIM
                                    : tb1 + ((size_t)(bank - 1) * NEXP + e) * HDIM;
    __half* C = g_H + (size_t)z * BATCH * HDIM;
    gemm_body<true, true, HDIM>(A, W, bias, C);
}

__global__ __launch_bounds__(NTH, 2)
void gemm2_kernel(const float* __restrict__ sb2, const float* __restrict__ tb2,
                  float* __restrict__ out)
{
    const int z = blockIdx.z, bank = z / NEXP, e = z - bank * NEXP;
    const __half* A = g_H + (size_t)z * BATCH * HDIM;
    const __half* W = g_W2h + (size_t)z * ODIM * HDIM;
    const float* bias = (bank == 0) ? sb2 + (size_t)e * ODIM
                                    : tb2 + ((size_t)(bank - 1) * NEXP + e) * ODIM;
    gemm_body<false, false, ODIM>(A, W, bias, out + (size_t)z * BATCH * ODIM);
}

// ---------------------------------------------------------------------------
// launch
// ---------------------------------------------------------------------------
extern "C" void kernel_launch(void* const* d_in, const int* in_sizes, int n_in,
                              void* d_out, int out_size)
{
    const float* share_x  = (const float*)d_in[0];
    const float* task_x0  = (const float*)d_in[1];
    const float* task_x1  = (const float*)d_in[2];
    const float* share_W1 = (const float*)d_in[3];
    const float* share_b1 = (const float*)d_in[4];
    const float* share_W2 = (const float*)d_in[5];
    const float* share_b2 = (const float*)d_in[6];
    const float* task_W1  = (const float*)d_in[7];
    const float* task_b1  = (const float*)d_in[8];
    const float* task_W2  = (const float*)d_in[9];
    const float* task_b2  = (const float*)d_in[10];
    float* out = (float*)d_out;

    // 1) convert inputs + transpose/convert weights to fp16
    const size_t nx4 = (size_t)3 * BATCH * HDIM / 4;
    cvt_x_kernel<<<(unsigned)((nx4 + 255) / 256), 256>>>(share_x, task_x0, task_x1);
    cvt_w_kernel<<<NZ * 256 + NZ * 64, dim3(32, 8)>>>(share_W1, task_W1, share_W2, task_W2);

    // 2) GEMMs
    gemm1_kernel<<<dim3(HDIM / BN, BATCH / BM, NZ), NTH>>>(share_b1, task_b1);
    gemm2_kernel<<<dim3(ODIM / BN, BATCH / BM, NZ), NTH>>>(share_b2, task_b2, out);
}